// round 16
// baseline (speedup 1.0000x reference)
#include <cuda_runtime.h>

// Fixed geometry: feats_r (3,1,64,48,84), feats_t (1,64,48,84),
// quantized_r (3,1,32,192,336); gaps=[16,15,14] -> nsearch=1 (ref0 dil=2),
// refs 1,2 plain dil-1, P=13 (N=169), MP=25.
#define H   48
#define W   84
#define HW  4032
#define C   64
#define CQ  32
#define SRC_HW (192*336)

// ---------------- scratch ----------------
__device__ float g_tT[HW*C];            // t, HWC
__device__ float g_rT[3][HW*C];         // refs, HWC
__device__ float g_qrT[3][HW*CQ];       // subsampled quantized refs, HWC
__device__ float g_part[25][HW][4];     // per-pp online-softmax partials (m,s,sy,sx)
__device__ float g_off[HW][2];          // off_y, off_x
__device__ float g_logits12[HW*338];    // refs 1,2 logits, PIXEL-major: [pix*338 + n]

// ---------------- K1a: feature transpose (64 x 4032 -> HWC) ----------------
__global__ void prep_feats_kernel(const float* __restrict__ fr,
                                  const float* __restrict__ ft) {
    __shared__ float tile[32][33];
    int t = blockIdx.z;                          // 0 = ft, 1..3 = refs
    const float* src = (t == 0) ? ft : (fr + (t - 1) * (C * HW));
    float* dst = (t == 0) ? g_tT : g_rT[t - 1];
    int pix0 = blockIdx.x * 32;
    int c0 = blockIdx.y * 32;
    for (int r = threadIdx.y; r < 32; r += 8)
        tile[r][threadIdx.x] = src[(c0 + r) * HW + pix0 + threadIdx.x];
    __syncthreads();
    for (int r = threadIdx.y; r < 32; r += 8)
        dst[(pix0 + r) * C + c0 + threadIdx.x] = tile[threadIdx.x][r];
}

// ---------------- K1b: quantized ref subsample -> HWC (coalesced) ----------
__global__ void prep_qr2_kernel(const float* __restrict__ qz) {
    __shared__ float sh[32 * 85];
    int a = blockIdx.y;
    int y = blockIdx.x;
    int tx = threadIdx.x, ty = threadIdx.y;
    const float* srcb = qz + a * (CQ * SRC_HW) + (4 * y) * 336;
    for (int c = ty; c < CQ; c += 8)
        for (int x = tx; x < W; x += 32)
            sh[c * 85 + x] = srcb[c * SRC_HW + 4 * x];
    __syncthreads();
    float* dstb = g_qrT[a] + y * (W * CQ);
    for (int x = ty; x < W; x += 8)
        dstb[x * CQ + tx] = sh[tx * 85 + x];
}

// ---------------- K2: MP=25 dil=2 correlation, register-tiled ----------------
#define RSW2 148
__global__ __launch_bounds__(96) void offs2_kernel() {
    int y = blockIdx.x;
    int gp = blockIdx.y;          // 0..24
    int pp = gp - 12;
    int yy = y + 2 * pp;
    bool rowok = (yy >= 0) && (yy < H);
    int tid = threadIdx.x;

    __shared__ __align__(16) float ts[32 * 84];   // [k][x]; reused as psh after
    __shared__ float rs[32 * RSW2];               // [k][xx+24], zero-padded

    int jt = (tid < 84) ? tid : 0;
    int qt = jt / 21;                   // 0..3  (slow)
    int xt = jt - 21 * qt;              // 0..20 (fast)

    float acc[4][8];
#pragma unroll
    for (int i = 0; i < 4; i++)
#pragma unroll
        for (int j = 0; j < 8; j++) acc[i][j] = 0.f;

    const float4* tp = reinterpret_cast<const float4*>(g_tT + y * (W * C));
    const float4* rp = reinterpret_cast<const float4*>(g_rT[0] + yy * (W * C));

    for (int i = tid; i < 32 * 64; i += 96) {
        int kk = i >> 6, j = i & 63;
        int col = (j < 24) ? j : (84 + j);
        rs[kk * RSW2 + col] = 0.f;
    }
    if (!rowok) {
        for (int i = tid; i < 32 * 84; i += 96) {
            int kk = i / 84, x = i - kk * 84;
            rs[kk * RSW2 + 24 + x] = 0.f;
        }
    }

    for (int kc = 0; kc < 2; kc++) {
        for (int i = tid; i < 84 * 8; i += 96) {
            int x = i >> 3, f = i & 7;
            float4 v = tp[x * 16 + kc * 8 + f];
            int c4 = f << 2;
            ts[(c4 + 0) * 84 + x] = v.x;
            ts[(c4 + 1) * 84 + x] = v.y;
            ts[(c4 + 2) * 84 + x] = v.z;
            ts[(c4 + 3) * 84 + x] = v.w;
        }
        if (rowok) {
            for (int i = tid; i < 84 * 8; i += 96) {
                int x = i >> 3, f = i & 7;
                float4 v = rp[x * 16 + kc * 8 + f];
                int c4 = f << 2;
                rs[(c4 + 0) * RSW2 + 24 + x] = v.x;
                rs[(c4 + 1) * RSW2 + 24 + x] = v.y;
                rs[(c4 + 2) * RSW2 + 24 + x] = v.z;
                rs[(c4 + 3) * RSW2 + 24 + x] = v.w;
            }
        }
        __syncthreads();

        int tbase = 4 * xt;
        int rbase = 4 * xt + 16 * qt;
#pragma unroll 4
        for (int k = 0; k < 32; k++) {
            float4 tq = *reinterpret_cast<const float4*>(ts + k * 84 + tbase);
            const float4* rr = reinterpret_cast<const float4*>(rs + k * RSW2 + rbase);
            float4 r0 = rr[0], r1 = rr[1], r2 = rr[2], r3 = rr[3], r4 = rr[4];
            float rv[20] = {r0.x,r0.y,r0.z,r0.w, r1.x,r1.y,r1.z,r1.w,
                            r2.x,r2.y,r2.z,r2.w, r3.x,r3.y,r3.z,r3.w,
                            r4.x,r4.y,r4.z,r4.w};
            float tv[4] = {tq.x, tq.y, tq.z, tq.w};
#pragma unroll
            for (int jx = 0; jx < 4; jx++)
#pragma unroll
                for (int jq = 0; jq < 8; jq++)
                    acc[jx][jq] += tv[jx] * rv[jx + 2 * jq];
        }
        __syncthreads();
    }

    float fpp = (float)pp;
    float m[4], s[4], sy[4], sx[4];
#pragma unroll
    for (int jx = 0; jx < 4; jx++) {
        m[jx] = -1e30f; s[jx] = 0.f; sy[jx] = 0.f; sx[jx] = 0.f;
#pragma unroll
        for (int jq = 0; jq < 8; jq++) {
            int qi = 8 * qt + jq;
            if (qi < 25) {
                float logit = acc[jx][jq];
                float fqq = (float)(qi - 12);
                if (logit > m[jx]) {
                    float e = __expf(m[jx] - logit);
                    s[jx] = s[jx] * e + 1.f;
                    sy[jx] = sy[jx] * e + fpp;
                    sx[jx] = sx[jx] * e + fqq;
                    m[jx] = logit;
                } else {
                    float e = __expf(logit - m[jx]);
                    s[jx] += e; sy[jx] += e * fpp; sx[jx] += e * fqq;
                }
            }
        }
    }

    float4* psh = reinterpret_cast<float4*>(ts);
    if (tid < 84) {
#pragma unroll
        for (int jx = 0; jx < 4; jx++)
            psh[(qt * 21 + xt) * 4 + jx] = make_float4(m[jx], s[jx], sy[jx], sx[jx]);
    }
    __syncthreads();
    if (tid < 84) {
        int px = tid;
        int mxt = px >> 2, mjx = px & 3;
        float4 a0 = psh[(0 * 21 + mxt) * 4 + mjx];
        float M = a0.x, S = a0.y, SY = a0.z, SX = a0.w;
#pragma unroll
        for (int u = 1; u < 4; u++) {
            float4 b = psh[(u * 21 + mxt) * 4 + mjx];
            if (b.x > M) {
                float e = __expf(M - b.x);
                S = S * e + b.y; SY = SY * e + b.z; SX = SX * e + b.w; M = b.x;
            } else {
                float e = __expf(b.x - M);
                S += b.y * e; SY += b.z * e; SX += b.w * e;
            }
        }
        int pix = y * W + px;
        g_part[gp][pix][0] = M;
        g_part[gp][pix][1] = S;
        g_part[gp][pix][2] = SY;
        g_part[gp][pix][3] = SX;
    }
}

// ---------------- K3: warp-per-pixel tree merge of 25 partials ----------------
__global__ __launch_bounds__(256) void offs_merge2_kernel() {
    int wid = threadIdx.x >> 5;
    int lane = threadIdx.x & 31;
    int pix = blockIdx.x * 8 + wid;      // 504*8 = 4032 exactly

    float m = -1e30f, s = 0.f, sy = 0.f, sx = 0.f;
    if (lane < 25) {
        float4 pm = *reinterpret_cast<const float4*>(&g_part[lane][pix][0]);
        m = pm.x; s = pm.y; sy = pm.z; sx = pm.w;
    }
#pragma unroll
    for (int o = 1; o <= 16; o <<= 1) {
        float m2 = __shfl_xor_sync(0xffffffffu, m, o);
        float s2 = __shfl_xor_sync(0xffffffffu, s, o);
        float sy2 = __shfl_xor_sync(0xffffffffu, sy, o);
        float sx2 = __shfl_xor_sync(0xffffffffu, sx, o);
        if (m2 > m) {
            float e = __expf(m - m2);
            s = s * e + s2; sy = sy * e + sy2; sx = sx * e + sx2; m = m2;
        } else {
            float e = __expf(m2 - m);
            s += s2 * e; sy += sy2 * e; sx += sx2 * e;
        }
    }
    if (lane == 0) {
        float inv = 1.f / s;
        g_off[pix][0] = 2.f * sy * inv;
        g_off[pix][1] = 2.f * sx * inv;
    }
}

// ---------------- K4: dil-1 correlations refs 1,2, register-tiled ----------------
#define RSW4 104
__global__ __launch_bounds__(168) void logits12b_kernel() {
    int y = blockIdx.x;
    int a0 = blockIdx.y * 2;
    int ref = blockIdx.z + 1;
    int tid = threadIdx.x;

    __shared__ float ts[32 * 84];          // [k][x]
    __shared__ float rs[2][32 * RSW4];     // [ap][k][xx+8], zero-padded

    int ap = tid / 84;                     // 0..1
    int rem = tid - ap * 84;
    int xt = rem >> 2;                     // 0..20
    int bt = rem & 3;                      // 0..3

    float acc[4][4];
#pragma unroll
    for (int i = 0; i < 4; i++)
#pragma unroll
        for (int j = 0; j < 4; j++) acc[i][j] = 0.f;

    const float4* tp = reinterpret_cast<const float4*>(g_tT + y * (W * C));

    for (int kc = 0; kc < 2; kc++) {
        for (int i = tid; i < 84 * 8; i += 168) {
            int x = i >> 3, f = i & 7;
            float4 v = tp[x * 16 + kc * 8 + f];
            int c4 = f << 2;
            ts[(c4 + 0) * 84 + x] = v.x;
            ts[(c4 + 1) * 84 + x] = v.y;
            ts[(c4 + 2) * 84 + x] = v.z;
            ts[(c4 + 3) * 84 + x] = v.w;
        }
        for (int aa = 0; aa < 2; aa++) {
            int yy = y + (a0 + aa) - 6;
            bool rowok = (yy >= 0) && (yy < H);
            if (rowok) {
                for (int i = tid; i < 32 * 20; i += 168) {
                    int kk = i / 20, j = i - kk * 20;
                    int col = (j < 8) ? j : (84 + j);
                    rs[aa][kk * RSW4 + col] = 0.f;
                }
                const float4* rp = reinterpret_cast<const float4*>(g_rT[ref] + yy * (W * C));
                for (int i = tid; i < 84 * 8; i += 168) {
                    int x = i >> 3, f = i & 7;
                    float4 v = rp[x * 16 + kc * 8 + f];
                    int c4 = f << 2;
                    rs[aa][(c4 + 0) * RSW4 + 8 + x] = v.x;
                    rs[aa][(c4 + 1) * RSW4 + 8 + x] = v.y;
                    rs[aa][(c4 + 2) * RSW4 + 8 + x] = v.z;
                    rs[aa][(c4 + 3) * RSW4 + 8 + x] = v.w;
                }
            } else {
                for (int i = tid; i < 32 * RSW4; i += 168) rs[aa][i] = 0.f;
            }
        }
        __syncthreads();

        int tbase = 4 * xt;
        int rbase0 = 4 * xt + 4 * bt;     // sh idx = rbase0 + jx + jb + 2
        const float* rsa = rs[ap];
#pragma unroll 4
        for (int k = 0; k < 32; k++) {
            float4 tq = *reinterpret_cast<const float4*>(ts + k * 84 + tbase);
            const float4* rr = reinterpret_cast<const float4*>(rsa + k * RSW4 + rbase0);
            float4 r0 = rr[0], r1 = rr[1], r2 = rr[2];
            float rv[12] = {r0.x,r0.y,r0.z,r0.w, r1.x,r1.y,r1.z,r1.w,
                            r2.x,r2.y,r2.z,r2.w};
            float tv[4] = {tq.x, tq.y, tq.z, tq.w};
#pragma unroll
            for (int jx = 0; jx < 4; jx++)
#pragma unroll
                for (int jb = 0; jb < 4; jb++)
                    acc[jx][jb] += tv[jx] * rv[jx + jb + 2];
        }
        __syncthreads();
    }

    int a = a0 + ap;
    if (a < 13) {
#pragma unroll
        for (int jx = 0; jx < 4; jx++) {
            int pix = y * W + 4 * xt + jx;
#pragma unroll
            for (int jb = 0; jb < 4; jb++) {
                int b = 4 * bt + jb;
                if (b < 13)
                    g_logits12[pix * 338 + (ref - 1) * 169 + a * 13 + b] = acc[jx][jb];
            }
        }
    }
}

// ---------------- K5: dual-pixel bilinear corr + softmax + output ----------
// 1024 threads = 2 independent 512-thread pixel halves (pix = 2b+h). Adjacent
// pixels share ~92% of their gather windows -> second pixel hits L1.
__global__ __launch_bounds__(1024) void final7_kernel(float* __restrict__ out) {
    int tid = threadIdx.x;
    int h = tid >> 9;            // pixel half 0/1
    int t = tid & 511;
    int wid = t >> 5;            // 0..15
    int lane = t & 31;
    int half = lane >> 4;        // 0/1
    int hl = lane & 15;          // 0..15

    int pix = blockIdx.x * 2 + h;    // W=84 even -> pair always same row
    int y = pix / W;
    int x = pix - y * W;

    __shared__ float lsh[2][507];
    __shared__ float Dsh[2][196];
    __shared__ float W0[2][196];
    __shared__ float red[2][16];
    __shared__ float oacc[2][16][32];

    float offy = g_off[pix][0];
    float offx = g_off[pix][1];
    float Yf = (float)y + offy;
    float Xf = (float)x + offx;
    float fYf = floorf(Yf), fXf = floorf(Xf);
    int fy = (int)fYf, fx = (int)fXf;
    float wy = Yf - fYf, wx = Xf - fXf;
    float c00 = (1.f - wy) * (1.f - wx);
    float c01 = (1.f - wy) * wx;
    float c10 = wy * (1.f - wx);
    float c11 = wy * wx;

    float4 t4 = reinterpret_cast<const float4*>(g_tT + pix * C)[hl];

    if (t < 338) lsh[h][169 + t] = g_logits12[pix * 338 + t];

    // 14x14 integer-grid dot field: fixed 7 iters, warp-uniform guard
#pragma unroll
    for (int i = 0; i < 7; i++) {
        int d = 2 * wid + half + 32 * i;
        if (d < 196) {
            int aa = d / 14, bb = d - aa * 14;
            int ry = fy + aa - 6, rx = fx + bb - 6;
            float v = 0.f;
            if ((unsigned)ry < (unsigned)H && (unsigned)rx < (unsigned)W) {
                float4 r4 = reinterpret_cast<const float4*>(g_rT[0] + (ry * W + rx) * C)[hl];
                v = t4.x * r4.x + t4.y * r4.y + t4.z * r4.z + t4.w * r4.w;
            }
#pragma unroll
            for (int o = 1; o <= 8; o <<= 1) v += __shfl_xor_sync(0xffffffffu, v, o);
            if (hl == 0) Dsh[h][d] = v;
        }
    }
    __syncthreads();

    if (t < 169) {
        int p = t / 13, q = t - p * 13;
        lsh[h][t] = c00 * Dsh[h][p * 14 + q] + c01 * Dsh[h][p * 14 + q + 1]
                  + c10 * Dsh[h][(p + 1) * 14 + q] + c11 * Dsh[h][(p + 1) * 14 + q + 1];
    }
    __syncthreads();

    float lm = (t < 507) ? lsh[h][t] : -1e30f;
#pragma unroll
    for (int o = 16; o; o >>= 1) lm = fmaxf(lm, __shfl_xor_sync(0xffffffffu, lm, o));
    if (lane == 0) red[h][wid] = lm;
    __syncthreads();
    float M = red[h][0];
#pragma unroll
    for (int i = 1; i < 16; i++) M = fmaxf(M, red[h][i]);
    __syncthreads();

    float ls = 0.f;
    if (t < 507) {
        float e = __expf(lsh[h][t] - M);
        lsh[h][t] = e;
        ls = e;
    }
#pragma unroll
    for (int o = 16; o; o >>= 1) ls += __shfl_xor_sync(0xffffffffu, ls, o);
    if (lane == 0) red[h][wid] = ls;
    __syncthreads();
    float S = 0.f;
#pragma unroll
    for (int i = 0; i < 16; i++) S += red[h][i];
    float invS = 1.f / S;

    if (t < 196) {
        int aa = t / 14, bb = t - aa * 14;
        float w00 = (aa < 13 && bb < 13) ? lsh[h][aa * 13 + bb] : 0.f;
        float w01 = (aa < 13 && bb >= 1) ? lsh[h][aa * 13 + bb - 1] : 0.f;
        float w10 = (aa >= 1 && bb < 13) ? lsh[h][(aa - 1) * 13 + bb] : 0.f;
        float w11 = (aa >= 1 && bb >= 1) ? lsh[h][(aa - 1) * 13 + bb - 1] : 0.f;
        W0[h][t] = c00 * w00 + c01 * w01 + c10 * w10 + c11 * w11;
    }
    __syncthreads();

    float acc = 0.f;
    for (int s = wid; s < 534; s += 16) {
        float wgt;
        int ry, rx;
        const float* src;
        if (s < 196) {
            int aa = s / 14, bb = s - aa * 14;
            wgt = W0[h][s];
            ry = fy + aa - 6; rx = fx + bb - 6;
            src = g_qrT[0];
        } else if (s < 365) {
            int n = s - 196;
            int p = n / 13, q = n - p * 13;
            wgt = lsh[h][169 + n];
            ry = y + p - 6; rx = x + q - 6;
            src = g_qrT[1];
        } else {
            int n = s - 365;
            int p = n / 13, q = n - p * 13;
            wgt = lsh[h][338 + n];
            ry = y + p - 6; rx = x + q - 6;
            src = g_qrT[2];
        }
        if ((unsigned)ry < (unsigned)H && (unsigned)rx < (unsigned)W)
            acc += wgt * src[(ry * W + rx) * CQ + lane];
    }
    oacc[h][wid][lane] = acc;
    __syncthreads();
    if (t < 32) {
        float o2 = 0.f;
#pragma unroll
        for (int wrp = 0; wrp < 16; wrp++) o2 += oacc[h][wrp][t];
        out[t * HW + pix] = o2 * invS;
    }
}

// ---------------- launch: fork/join so offs-path overlaps logits12b --------
extern "C" void kernel_launch(void* const* d_in, const int* in_sizes, int n_in,
                              void* d_out, int out_size) {
    const float* fr = (const float*)d_in[0];
    const float* ft = (const float*)d_in[1];
    const float* qz = (const float*)d_in[2];
    float* out = (float*)d_out;

    static cudaStream_t s2 = nullptr;
    static cudaEvent_t eFork = nullptr, eJoin = nullptr;
    if (s2 == nullptr) {
        cudaStreamCreateWithFlags(&s2, cudaStreamNonBlocking);
        cudaEventCreateWithFlags(&eFork, cudaEventDisableTiming);
        cudaEventCreateWithFlags(&eJoin, cudaEventDisableTiming);
    }

    prep_qr2_kernel<<<dim3(48, 3), dim3(32, 8)>>>(qz);
    prep_feats_kernel<<<dim3(126, 2, 4), dim3(32, 8)>>>(fr, ft);

    cudaEventRecord(eFork, 0);
    cudaStreamWaitEvent(s2, eFork, 0);
    logits12b_kernel<<<dim3(48, 7, 2), 168, 0, s2>>>();
    cudaEventRecord(eJoin, s2);

    offs2_kernel<<<dim3(48, 25), 96>>>();
    offs_merge2_kernel<<<504, 256>>>();

    cudaStreamWaitEvent(0, eJoin, 0);
    final7_kernel<<<HW / 2, 1024>>>(out);
}

// round 17
// speedup vs baseline: 1.0815x; 1.0815x over previous
#include <cuda_runtime.h>

// Fixed geometry: feats_r (3,1,64,48,84), feats_t (1,64,48,84),
// quantized_r (3,1,32,192,336); gaps=[16,15,14] -> nsearch=1 (ref0 dil=2),
// refs 1,2 plain dil-1, P=13 (N=169), MP=25.
#define H   48
#define W   84
#define HW  4032
#define C   64
#define CQ  32
#define SRC_HW (192*336)

// ---------------- scratch ----------------
__device__ float g_tT[HW*C];            // t, HWC
__device__ float g_rT[3][HW*C];         // refs, HWC
__device__ float g_qrT[3][HW*CQ];       // subsampled quantized refs, HWC
__device__ float g_part[25][HW][4];     // per-pp online-softmax partials (m,s,sy,sx)
__device__ float g_off[HW][2];          // off_y, off_x
__device__ float g_logits12[HW*338];    // refs 1,2 logits, PIXEL-major: [pix*338 + n]

// ---------------- K1a: feature transpose (64 x 4032 -> HWC) ----------------
__global__ void prep_feats_kernel(const float* __restrict__ fr,
                                  const float* __restrict__ ft) {
    __shared__ float tile[32][33];
    int t = blockIdx.z;                          // 0 = ft, 1..3 = refs
    const float* src = (t == 0) ? ft : (fr + (t - 1) * (C * HW));
    float* dst = (t == 0) ? g_tT : g_rT[t - 1];
    int pix0 = blockIdx.x * 32;
    int c0 = blockIdx.y * 32;
    for (int r = threadIdx.y; r < 32; r += 8)
        tile[r][threadIdx.x] = src[(c0 + r) * HW + pix0 + threadIdx.x];
    __syncthreads();
    for (int r = threadIdx.y; r < 32; r += 8)
        dst[(pix0 + r) * C + c0 + threadIdx.x] = tile[threadIdx.x][r];
}

// ---------------- K1b: quantized ref subsample -> HWC (coalesced) ----------
__global__ void prep_qr2_kernel(const float* __restrict__ qz) {
    __shared__ float sh[32 * 85];
    int a = blockIdx.y;
    int y = blockIdx.x;
    int tx = threadIdx.x, ty = threadIdx.y;
    const float* srcb = qz + a * (CQ * SRC_HW) + (4 * y) * 336;
    for (int c = ty; c < CQ; c += 8)
        for (int x = tx; x < W; x += 32)
            sh[c * 85 + x] = srcb[c * SRC_HW + 4 * x];
    __syncthreads();
    float* dstb = g_qrT[a] + y * (W * CQ);
    for (int x = ty; x < W; x += 8)
        dstb[x * CQ + tx] = sh[tx * 85 + x];
}

// ---------------- K2: MP=25 dil=2 correlation, register-tiled ----------------
// grid (48, 25). 96 threads; 84 jobs: xt = jt%21 (fast), qt = jt/21.
// Channels in 4 chunks of 16 -> smem 14.8KB -> ~2x occupancy vs 32-chunk.
#define RSW2 148
#define KCH  16
__global__ __launch_bounds__(96) void offs2_kernel() {
    int y = blockIdx.x;
    int gp = blockIdx.y;          // 0..24
    int pp = gp - 12;
    int yy = y + 2 * pp;
    bool rowok = (yy >= 0) && (yy < H);
    int tid = threadIdx.x;

    __shared__ __align__(16) float ts[KCH * 84];  // [k][x]; reused as psh after
    __shared__ float rs[KCH * RSW2];              // [k][xx+24], zero-padded

    int jt = (tid < 84) ? tid : 0;
    int qt = jt / 21;                   // 0..3  (slow)
    int xt = jt - 21 * qt;              // 0..20 (fast)

    float acc[4][8];
#pragma unroll
    for (int i = 0; i < 4; i++)
#pragma unroll
        for (int j = 0; j < 8; j++) acc[i][j] = 0.f;

    const float4* tp = reinterpret_cast<const float4*>(g_tT + y * (W * C));
    const float4* rp = reinterpret_cast<const float4*>(g_rT[0] + yy * (W * C));

    // zero rs borders once (kc-invariant): cols [0,24) U [108,148)
    for (int i = tid; i < KCH * 64; i += 96) {
        int kk = i >> 6, j = i & 63;
        int col = (j < 24) ? j : (84 + j);
        rs[kk * RSW2 + col] = 0.f;
    }
    if (!rowok) {
        for (int i = tid; i < KCH * 84; i += 96) {
            int kk = i / 84, x = i - kk * 84;
            rs[kk * RSW2 + 24 + x] = 0.f;
        }
    }

    for (int kc = 0; kc < 4; kc++) {
        // fill ts chunk (channels kc*16 .. +16): 84*4 float4
        for (int i = tid; i < 84 * 4; i += 96) {
            int x = i >> 2, f = i & 3;
            float4 v = tp[x * 16 + kc * 4 + f];
            int c4 = f << 2;
            ts[(c4 + 0) * 84 + x] = v.x;
            ts[(c4 + 1) * 84 + x] = v.y;
            ts[(c4 + 2) * 84 + x] = v.z;
            ts[(c4 + 3) * 84 + x] = v.w;
        }
        if (rowok) {
            for (int i = tid; i < 84 * 4; i += 96) {
                int x = i >> 2, f = i & 3;
                float4 v = rp[x * 16 + kc * 4 + f];
                int c4 = f << 2;
                rs[(c4 + 0) * RSW2 + 24 + x] = v.x;
                rs[(c4 + 1) * RSW2 + 24 + x] = v.y;
                rs[(c4 + 2) * RSW2 + 24 + x] = v.z;
                rs[(c4 + 3) * RSW2 + 24 + x] = v.w;
            }
        }
        __syncthreads();

        int tbase = 4 * xt;
        int rbase = 4 * xt + 16 * qt;   // sh idx = rbase + jx + 2jq
#pragma unroll 4
        for (int k = 0; k < KCH; k++) {
            float4 tq = *reinterpret_cast<const float4*>(ts + k * 84 + tbase);
            const float4* rr = reinterpret_cast<const float4*>(rs + k * RSW2 + rbase);
            float4 r0 = rr[0], r1 = rr[1], r2 = rr[2], r3 = rr[3], r4 = rr[4];
            float rv[20] = {r0.x,r0.y,r0.z,r0.w, r1.x,r1.y,r1.z,r1.w,
                            r2.x,r2.y,r2.z,r2.w, r3.x,r3.y,r3.z,r3.w,
                            r4.x,r4.y,r4.z,r4.w};
            float tv[4] = {tq.x, tq.y, tq.z, tq.w};
#pragma unroll
            for (int jx = 0; jx < 4; jx++)
#pragma unroll
                for (int jq = 0; jq < 8; jq++)
                    acc[jx][jq] += tv[jx] * rv[jx + 2 * jq];
        }
        __syncthreads();
    }

    // per-jx online softmax over valid qi
    float fpp = (float)pp;
    float m[4], s[4], sy[4], sx[4];
#pragma unroll
    for (int jx = 0; jx < 4; jx++) {
        m[jx] = -1e30f; s[jx] = 0.f; sy[jx] = 0.f; sx[jx] = 0.f;
#pragma unroll
        for (int jq = 0; jq < 8; jq++) {
            int qi = 8 * qt + jq;
            if (qi < 25) {
                float logit = acc[jx][jq];
                float fqq = (float)(qi - 12);
                if (logit > m[jx]) {
                    float e = __expf(m[jx] - logit);
                    s[jx] = s[jx] * e + 1.f;
                    sy[jx] = sy[jx] * e + fpp;
                    sx[jx] = sx[jx] * e + fqq;
                    m[jx] = logit;
                } else {
                    float e = __expf(logit - m[jx]);
                    s[jx] += e; sy[jx] += e * fpp; sx[jx] += e * fqq;
                }
            }
        }
    }

    // merge across qt via smem (overlaid on ts; 84*4 float4 = 1344 floats = ts)
    float4* psh = reinterpret_cast<float4*>(ts);
    if (tid < 84) {
#pragma unroll
        for (int jx = 0; jx < 4; jx++)
            psh[(qt * 21 + xt) * 4 + jx] = make_float4(m[jx], s[jx], sy[jx], sx[jx]);
    }
    __syncthreads();
    if (tid < 84) {
        int px = tid;
        int mxt = px >> 2, mjx = px & 3;
        float4 a0 = psh[(0 * 21 + mxt) * 4 + mjx];
        float M = a0.x, S = a0.y, SY = a0.z, SX = a0.w;
#pragma unroll
        for (int u = 1; u < 4; u++) {
            float4 b = psh[(u * 21 + mxt) * 4 + mjx];
            if (b.x > M) {
                float e = __expf(M - b.x);
                S = S * e + b.y; SY = SY * e + b.z; SX = SX * e + b.w; M = b.x;
            } else {
                float e = __expf(b.x - M);
                S += b.y * e; SY += b.z * e; SX += b.w * e;
            }
        }
        int pix = y * W + px;
        g_part[gp][pix][0] = M;
        g_part[gp][pix][1] = S;
        g_part[gp][pix][2] = SY;
        g_part[gp][pix][3] = SX;
    }
}

// ---------------- K3: warp-per-pixel tree merge of 25 partials ----------------
__global__ __launch_bounds__(256) void offs_merge2_kernel() {
    int wid = threadIdx.x >> 5;
    int lane = threadIdx.x & 31;
    int pix = blockIdx.x * 8 + wid;      // 504*8 = 4032 exactly

    float m = -1e30f, s = 0.f, sy = 0.f, sx = 0.f;
    if (lane < 25) {
        float4 pm = *reinterpret_cast<const float4*>(&g_part[lane][pix][0]);
        m = pm.x; s = pm.y; sy = pm.z; sx = pm.w;
    }
#pragma unroll
    for (int o = 1; o <= 16; o <<= 1) {
        float m2 = __shfl_xor_sync(0xffffffffu, m, o);
        float s2 = __shfl_xor_sync(0xffffffffu, s, o);
        float sy2 = __shfl_xor_sync(0xffffffffu, sy, o);
        float sx2 = __shfl_xor_sync(0xffffffffu, sx, o);
        if (m2 > m) {
            float e = __expf(m - m2);
            s = s * e + s2; sy = sy * e + sy2; sx = sx * e + sx2; m = m2;
        } else {
            float e = __expf(m2 - m);
            s += s2 * e; sy += sy2 * e; sx += sx2 * e;
        }
    }
    if (lane == 0) {
        float inv = 1.f / s;
        g_off[pix][0] = 2.f * sy * inv;
        g_off[pix][1] = 2.f * sx * inv;
    }
}

// ---------------- K4: dil-1 correlations refs 1,2, register-tiled ----------------
// Channels in 4 chunks of 16; border zeroing hoisted. smem 18.7KB.
#define RSW4 104
__global__ __launch_bounds__(168) void logits12b_kernel() {
    int y = blockIdx.x;
    int a0 = blockIdx.y * 2;
    int ref = blockIdx.z + 1;
    int tid = threadIdx.x;

    __shared__ float ts[KCH * 84];           // [k][x]
    __shared__ float rs[2][KCH * RSW4];      // [ap][k][xx+8], zero-padded

    int ap = tid / 84;                     // 0..1
    int rem = tid - ap * 84;
    int xt = rem >> 2;                     // 0..20
    int bt = rem & 3;                      // 0..3

    float acc[4][4];
#pragma unroll
    for (int i = 0; i < 4; i++)
#pragma unroll
        for (int j = 0; j < 4; j++) acc[i][j] = 0.f;

    const float4* tp = reinterpret_cast<const float4*>(g_tT + y * (W * C));

    bool rowokA[2];
#pragma unroll
    for (int aa = 0; aa < 2; aa++) {
        int yy = y + (a0 + aa) - 6;
        rowokA[aa] = (yy >= 0) && (yy < H);
        if (rowokA[aa]) {
            // zero borders once: cols [0,8) U [92,104) -> 20 cols per k-row
            for (int i = tid; i < KCH * 20; i += 168) {
                int kk = i / 20, j = i - kk * 20;
                int col = (j < 8) ? j : (84 + j);
                rs[aa][kk * RSW4 + col] = 0.f;
            }
        } else {
            for (int i = tid; i < KCH * RSW4; i += 168) rs[aa][i] = 0.f;
        }
    }

    for (int kc = 0; kc < 4; kc++) {
        for (int i = tid; i < 84 * 4; i += 168) {
            int x = i >> 2, f = i & 3;
            float4 v = tp[x * 16 + kc * 4 + f];
            int c4 = f << 2;
            ts[(c4 + 0) * 84 + x] = v.x;
            ts[(c4 + 1) * 84 + x] = v.y;
            ts[(c4 + 2) * 84 + x] = v.z;
            ts[(c4 + 3) * 84 + x] = v.w;
        }
        for (int aa = 0; aa < 2; aa++) {
            if (rowokA[aa]) {
                int yy = y + (a0 + aa) - 6;
                const float4* rp = reinterpret_cast<const float4*>(g_rT[ref] + yy * (W * C));
                for (int i = tid; i < 84 * 4; i += 168) {
                    int x = i >> 2, f = i & 3;
                    float4 v = rp[x * 16 + kc * 4 + f];
                    int c4 = f << 2;
                    rs[aa][(c4 + 0) * RSW4 + 8 + x] = v.x;
                    rs[aa][(c4 + 1) * RSW4 + 8 + x] = v.y;
                    rs[aa][(c4 + 2) * RSW4 + 8 + x] = v.z;
                    rs[aa][(c4 + 3) * RSW4 + 8 + x] = v.w;
                }
            }
        }
        __syncthreads();

        int tbase = 4 * xt;
        int rbase0 = 4 * xt + 4 * bt;     // sh idx = rbase0 + jx + jb + 2
        const float* rsa = rs[ap];
#pragma unroll 4
        for (int k = 0; k < KCH; k++) {
            float4 tq = *reinterpret_cast<const float4*>(ts + k * 84 + tbase);
            const float4* rr = reinterpret_cast<const float4*>(rsa + k * RSW4 + rbase0);
            float4 r0 = rr[0], r1 = rr[1], r2 = rr[2];
            float rv[12] = {r0.x,r0.y,r0.z,r0.w, r1.x,r1.y,r1.z,r1.w,
                            r2.x,r2.y,r2.z,r2.w};
            float tv[4] = {tq.x, tq.y, tq.z, tq.w};
#pragma unroll
            for (int jx = 0; jx < 4; jx++)
#pragma unroll
                for (int jb = 0; jb < 4; jb++)
                    acc[jx][jb] += tv[jx] * rv[jx + jb + 2];
        }
        __syncthreads();
    }

    int a = a0 + ap;
    if (a < 13) {
#pragma unroll
        for (int jx = 0; jx < 4; jx++) {
            int pix = y * W + 4 * xt + jx;
#pragma unroll
            for (int jb = 0; jb < 4; jb++) {
                int b = 4 * bt + jb;
                if (b < 13)
                    g_logits12[pix * 338 + (ref - 1) * 169 + a * 13 + b] = acc[jx][jb];
            }
        }
    }
}

// ---------------- K5: bilinear corr (ref0) + softmax(507) + output ----------
// 512 threads/block, one pixel per block (the 190.5us config).
__global__ __launch_bounds__(512) void final3_kernel(float* __restrict__ out) {
    int pix = blockIdx.x;
    int y = pix / W;
    int x = pix - y * W;
    int tid = threadIdx.x;
    int wid = tid >> 5;          // 0..15
    int lane = tid & 31;
    int half = lane >> 4;        // 0/1
    int hl = lane & 15;          // 0..15

    __shared__ float lsh[507];
    __shared__ float Dsh[196];
    __shared__ float W0[196];
    __shared__ float red[16];
    __shared__ float oacc[16][32];

    float offy = g_off[pix][0];
    float offx = g_off[pix][1];
    float Yf = (float)y + offy;
    float Xf = (float)x + offx;
    float fYf = floorf(Yf), fXf = floorf(Xf);
    int fy = (int)fYf, fx = (int)fXf;
    float wy = Yf - fYf, wx = Xf - fXf;
    float c00 = (1.f - wy) * (1.f - wx);
    float c01 = (1.f - wy) * wx;
    float c10 = wy * (1.f - wx);
    float c11 = wy * wx;

    float4 t4 = reinterpret_cast<const float4*>(g_tT + pix * C)[hl];

    if (tid < 338) lsh[169 + tid] = g_logits12[pix * 338 + tid];

#pragma unroll
    for (int i = 0; i < 7; i++) {
        int d = 2 * wid + half + 32 * i;
        if (d < 196) {
            int aa = d / 14, bb = d - aa * 14;
            int ry = fy + aa - 6, rx = fx + bb - 6;
            float v = 0.f;
            if ((unsigned)ry < (unsigned)H && (unsigned)rx < (unsigned)W) {
                float4 r4 = reinterpret_cast<const float4*>(g_rT[0] + (ry * W + rx) * C)[hl];
                v = t4.x * r4.x + t4.y * r4.y + t4.z * r4.z + t4.w * r4.w;
            }
#pragma unroll
            for (int o = 1; o <= 8; o <<= 1) v += __shfl_xor_sync(0xffffffffu, v, o);
            if (hl == 0) Dsh[d] = v;
        }
    }
    __syncthreads();

    if (tid < 169) {
        int p = tid / 13, q = tid - p * 13;
        lsh[tid] = c00 * Dsh[p * 14 + q] + c01 * Dsh[p * 14 + q + 1]
                 + c10 * Dsh[(p + 1) * 14 + q] + c11 * Dsh[(p + 1) * 14 + q + 1];
    }
    __syncthreads();

    float lm = (tid < 507) ? lsh[tid] : -1e30f;
#pragma unroll
    for (int o = 16; o; o >>= 1) lm = fmaxf(lm, __shfl_xor_sync(0xffffffffu, lm, o));
    if (lane == 0) red[wid] = lm;
    __syncthreads();
    float M = red[0];
#pragma unroll
    for (int i = 1; i < 16; i++) M = fmaxf(M, red[i]);
    __syncthreads();

    float ls = 0.f;
    if (tid < 507) {
        float e = __expf(lsh[tid] - M);
        lsh[tid] = e;
        ls = e;
    }
#pragma unroll
    for (int o = 16; o; o >>= 1) ls += __shfl_xor_sync(0xffffffffu, ls, o);
    if (lane == 0) red[wid] = ls;
    __syncthreads();
    float S = 0.f;
#pragma unroll
    for (int i = 0; i < 16; i++) S += red[i];
    float invS = 1.f / S;

    if (tid < 196) {
        int aa = tid / 14, bb = tid - aa * 14;
        float w00 = (aa < 13 && bb < 13) ? lsh[aa * 13 + bb] : 0.f;
        float w01 = (aa < 13 && bb >= 1) ? lsh[aa * 13 + bb - 1] : 0.f;
        float w10 = (aa >= 1 && bb < 13) ? lsh[(aa - 1) * 13 + bb] : 0.f;
        float w11 = (aa >= 1 && bb >= 1) ? lsh[(aa - 1) * 13 + bb - 1] : 0.f;
        W0[tid] = c00 * w00 + c01 * w01 + c10 * w10 + c11 * w11;
    }
    __syncthreads();

    float acc = 0.f;
    for (int s = wid; s < 534; s += 16) {
        float wgt;
        int ry, rx;
        const float* src;
        if (s < 196) {
            int aa = s / 14, bb = s - aa * 14;
            wgt = W0[s];
            ry = fy + aa - 6; rx = fx + bb - 6;
            src = g_qrT[0];
        } else if (s < 365) {
            int n = s - 196;
            int p = n / 13, q = n - p * 13;
            wgt = lsh[169 + n];
            ry = y + p - 6; rx = x + q - 6;
            src = g_qrT[1];
        } else {
            int n = s - 365;
            int p = n / 13, q = n - p * 13;
            wgt = lsh[338 + n];
            ry = y + p - 6; rx = x + q - 6;
            src = g_qrT[2];
        }
        if ((unsigned)ry < (unsigned)H && (unsigned)rx < (unsigned)W)
            acc += wgt * src[(ry * W + rx) * CQ + lane];
    }
    oacc[wid][lane] = acc;
    __syncthreads();
    if (tid < 32) {
        float t = 0.f;
#pragma unroll
        for (int wrp = 0; wrp < 16; wrp++) t += oacc[wrp][tid];
        out[tid * HW + pix] = t * invS;
    }
}

// ---------------- launch: fork/join so offs-path overlaps logits12b --------
extern "C" void kernel_launch(void* const* d_in, const int* in_sizes, int n_in,
                              void* d_out, int out_size) {
    const float* fr = (const float*)d_in[0];
    const float* ft = (const float*)d_in[1];
    const float* qz = (const float*)d_in[2];
    float* out = (float*)d_out;

    static cudaStream_t s2 = nullptr;
    static cudaEvent_t eFork = nullptr, eJoin = nullptr;
    if (s2 == nullptr) {
        cudaStreamCreateWithFlags(&s2, cudaStreamNonBlocking);
        cudaEventCreateWithFlags(&eFork, cudaEventDisableTiming);
        cudaEventCreateWithFlags(&eJoin, cudaEventDisableTiming);
    }

    prep_qr2_kernel<<<dim3(48, 3), dim3(32, 8)>>>(qz);
    prep_feats_kernel<<<dim3(126, 2, 4), dim3(32, 8)>>>(fr, ft);

    cudaEventRecord(eFork, 0);
    cudaStreamWaitEvent(s2, eFork, 0);
    logits12b_kernel<<<dim3(48, 7, 2), 168, 0, s2>>>();
    cudaEventRecord(eJoin, s2);

    offs2_kernel<<<dim3(48, 25), 96>>>();
    offs_merge2_kernel<<<504, 256>>>();

    cudaStreamWaitEvent(0, eJoin, 0);
    final3_kernel<<<HW, 512>>>(out);
}